// round 8
// baseline (speedup 1.0000x reference)
#include <cuda_runtime.h>

#define D         128
#define U         256
#define KC        10
#define GRID_B    148
#define WB        16             // warps
#define SPW       4              // spikes per warp per round
#define SROUND    64             // spikes per round
#define CAP       20             // max entries per unit per round
#define XROW      128            // staged x row stride (floats)
#define PROW      132            // g_part row stride (floats, 16B aligned)
#define THREADS_B (WB * 32)

__device__ __align__(16) float g_w[U * D];       // inv_var * mu  (128 KB)
__device__ float g_b[U];
__device__ __align__(16) float g_part[GRID_B * U * PROW];
__device__ int   g_c64;

__device__ __forceinline__ unsigned smem_u32(const void* p) {
    return (unsigned)__cvta_generic_to_shared(p);
}

// ---------------- prep (+ dtype probe in block 0) ---------------------------
__global__ void prep_kernel(const float* __restrict__ means,
                            const float* __restrict__ lnv,
                            const float* __restrict__ lp,
                            const int* __restrict__ candw, int probe_words) {
    int u = blockIdx.x, d = threadIdx.x;
    float iv = expf(-lnv[d]);
    float m  = means[u * D + d];
    float wv = iv * m;
    g_w[u * D + d] = wv;
    float p = wv * m;
    #pragma unroll
    for (int o = 16; o; o >>= 1) p += __shfl_xor_sync(0xffffffffu, p, o);
    __shared__ float red[4];
    __shared__ int any;
    if (threadIdx.x == 0) any = 0;
    if ((threadIdx.x & 31) == 0) red[threadIdx.x >> 5] = p;
    __syncthreads();
    if (threadIdx.x == 0)
        g_b[u] = -0.5f * (red[0] + red[1] + red[2] + red[3]) + lp[u];
    if (blockIdx.x == 0) {
        // int64 little-endian -> all odd 32-bit words are zero
        for (int i = threadIdx.x * 2 + 1; i < probe_words; i += 2 * D)
            if (candw[i] != 0) any = 1;
        __syncthreads();
        if (threadIdx.x == 0) g_c64 = (any == 0) ? 1 : 0;
    }
}

// ---------------- fused E-step: logits + softmax + scatter ------------------
// Slice scheme (phase 1): lane = 8*g + i; pass p computes candidates
// k = 4p+g for 4 groups at once; lane i covers dims [16i,16i+16).
// Scatter: warp w owns units [16w,16w+16); lane holds dims [4l,4l+4).
__global__ void __launch_bounds__(THREADS_B, 1)
fused_kernel(const float* __restrict__ x, const int* __restrict__ candw,
             int n, int chunk) {
    extern __shared__ float sm[];
    float* xs   = sm;                                // 2*SROUND*XROW (64 KB)
    int2*  ent  = (int2*)(xs + 2 * SROUND * XROW);   // U*CAP         (40 KB)
    int*   cnt  = (int*)(ent + U * CAP);             // U
    float* cntF = (float*)(cnt + U);                 // U

    const int tid  = threadIdx.x, lane = tid & 31, w = tid >> 5;
    const int g    = lane >> 3;
    const int i    = lane & 7;
    const int s64  = g_c64;

    float4 acc[16];
    #pragma unroll
    for (int j = 0; j < 16; j++) acc[j] = make_float4(0.f, 0.f, 0.f, 0.f);
    for (int t = tid; t < U; t += THREADS_B) { cnt[t] = 0; cntF[t] = 0.f; }

    const int base   = blockIdx.x * chunk;
    const int end    = (base + chunk < n) ? (base + chunk) : n;
    const int rounds = (end - base + SROUND - 1) / SROUND;

    // ---- prologue: cand regs + x copies for round 0 (buf 0) ----
    int myu[SPW];
    #pragma unroll
    for (int j = 0; j < SPW; j++) {
        int sl = w * SPW + j;
        int s  = base + sl;
        myu[j] = -1;
        if (s < end) {
            unsigned dst = smem_u32(xs + sl * XROW + lane * 4);
            asm volatile("cp.async.cg.shared.global [%0], [%1], 16;\n"
                         :: "r"(dst), "l"(x + (size_t)s * D + lane * 4));
            if (lane < KC)
                myu[j] = __ldcs(&candw[((size_t)s * KC + lane) << s64]);
        }
    }
    asm volatile("cp.async.commit_group;\n");
    asm volatile("cp.async.wait_group 0;\n" ::: "memory");
    __syncthreads();

    for (int rd = 0; rd < rounds; rd++) {
        const int    rb  = base + rd * SROUND;
        const float* xsb = xs + (rd & 1) * SROUND * XROW;

        // ---- phase 1: logits + softmax + entry write for my SPW spikes ----
        #pragma unroll 1
        for (int j = 0; j < SPW; j++) {
            int s = rb + w * SPW + j;
            if (s >= end) break;
            int sl = w * SPW + j;

            const float4* xr = (const float4*)(xsb + sl * XROW) + 4 * i;
            float4 xa0 = xr[0], xa1 = xr[1], xa2 = xr[2], xa3 = xr[3];

            int mu = myu[j];
            float lg[3];
            int u_mine = -1;
            #pragma unroll
            for (int p = 0; p < 3; p++) {
                int  k  = 4 * p + g;
                bool kv = (k < KC);
                int  u  = __shfl_sync(0xffffffffu, mu, kv ? k : 0);
                bool uv = kv && ((unsigned)u < U);
                int  uc = uv ? u : 0;
                const float4* wr = (const float4*)g_w + uc * 32 + 4 * i;
                float4 w0 = wr[0], w1 = wr[1], w2 = wr[2], w3 = wr[3];
                float dot =
                    fmaf(w0.x, xa0.x, fmaf(w0.y, xa0.y, fmaf(w0.z, xa0.z,
                    fmaf(w0.w, xa0.w, fmaf(w1.x, xa1.x, fmaf(w1.y, xa1.y,
                    fmaf(w1.z, xa1.z, fmaf(w1.w, xa1.w, fmaf(w2.x, xa2.x,
                    fmaf(w2.y, xa2.y, fmaf(w2.z, xa2.z, fmaf(w2.w, xa2.w,
                    fmaf(w3.x, xa3.x, fmaf(w3.y, xa3.y, fmaf(w3.z, xa3.z,
                         w3.w * xa3.w)))))))))))))));
                dot += __shfl_xor_sync(0xffffffffu, dot, 4);
                dot += __shfl_xor_sync(0xffffffffu, dot, 2);
                dot += __shfl_xor_sync(0xffffffffu, dot, 1);
                lg[p] = uv ? dot + __ldg(&g_b[uc]) : -1e30f;
                if (p == i && uv) u_mine = u;   // lanes i<3 keep their unit
            }

            float m = fmaxf(fmaxf(lg[0], lg[1]), fmaxf(lg[2], -2.0f));
            m = fmaxf(m, __shfl_xor_sync(0xffffffffu, m, 8));
            m = fmaxf(m, __shfl_xor_sync(0xffffffffu, m, 16));

            float e0 = __expf(lg[0] - m);
            float e1 = __expf(lg[1] - m);
            float e2 = __expf(lg[2] - m);
            float sl_ = e0 + e1 + e2;    // identical across 8 lanes of group
            sl_ += __shfl_xor_sync(0xffffffffu, sl_, 8);
            sl_ += __shfl_xor_sync(0xffffffffu, sl_, 16);
            float inv = 1.f / (sl_ + __expf(-2.0f - m));

            if (i < 3 && (4 * i + g) < KC && u_mine >= 0) {
                float r = ((i == 0) ? e0 : ((i == 1) ? e1 : e2)) * inv;
                int slot = atomicAdd(&cnt[u_mine], 1);
                if (slot < CAP) {
                    int2 e;
                    e.x = sl;
                    e.y = __float_as_int(r);
                    ent[u_mine * CAP + slot] = e;
                }
            }
        }

        // ---- prefetch cand for rd+1; issue x copies for rd+1 (buf^1) ----
        #pragma unroll
        for (int j = 0; j < SPW; j++) {
            int s = rb + SROUND + w * SPW + j;
            myu[j] = (s < end && lane < KC)
                   ? __ldcs(&candw[((size_t)s * KC + lane) << s64]) : -1;
        }
        if (rd + 1 < rounds) {
            float* xsn = xs + ((rd + 1) & 1) * SROUND * XROW;
            #pragma unroll
            for (int j = 0; j < SPW; j++) {
                int sl = w * SPW + j;
                int s  = rb + SROUND + sl;
                if (s < end) {
                    unsigned dst = smem_u32(xsn + sl * XROW + lane * 4);
                    asm volatile("cp.async.cg.shared.global [%0], [%1], 16;\n"
                                 :: "r"(dst), "l"(x + (size_t)s * D + lane * 4));
                }
            }
        }
        asm volatile("cp.async.commit_group;\n");
        __syncthreads();                       // ent/cnt writes visible

        // ---- drain: warp w -> its 16 units, register accumulators ----
        #pragma unroll 1
        for (int j2 = 0; j2 < 16; j2++) {
            int u = w * 16 + j2;
            int c = cnt[u];
            if (c == 0) continue;
            if (lane == 0) cnt[u] = 0;         // owner-exclusive reset
            c = (c < CAP) ? c : CAP;
            float csum = 0.f;
            const int2* eb = ent + u * CAP;
            for (int q = 0; q < c; q++) {
                int2 e = eb[q];
                float r = __int_as_float(e.y);
                float4 xv = ((const float4*)(xsb + e.x * XROW))[lane];
                acc[j2].x = fmaf(r, xv.x, acc[j2].x);
                acc[j2].y = fmaf(r, xv.y, acc[j2].y);
                acc[j2].z = fmaf(r, xv.z, acc[j2].z);
                acc[j2].w = fmaf(r, xv.w, acc[j2].w);
                csum += r;
            }
            if (lane == 0) cntF[u] += csum;
        }
        asm volatile("cp.async.wait_group 0;\n" ::: "memory"); // buf^1 arrived
        __syncthreads();          // next buf + cnt resets visible block-wide
    }

    // ---- flush register stats ----
    float* pb = g_part + (size_t)blockIdx.x * (U * PROW);
    #pragma unroll
    for (int j = 0; j < 16; j++) {
        int u = w * 16 + j;
        ((float4*)(pb + u * PROW))[lane] = acc[j];
        if (lane == 0) pb[u * PROW + 128] = cntF[u];
    }
}

// ---------------- final reduction: 64 outputs x 8 slices per block ----------
__global__ void reduce_kernel(float* __restrict__ out) {
    __shared__ float red[8][64];
    const int ol    = threadIdx.x & 63;
    const int slice = threadIdx.x >> 6;          // 0..7
    const int o     = blockIdx.x * 64 + ol;
    if (o >= U * (D + 1)) return;
    const int u = o / (D + 1);
    const int d = o - u * (D + 1);
    const int idx = u * PROW + d;
    const int pb = slice * 19;
    const int pe = (pb + 19 < GRID_B) ? pb + 19 : GRID_B;
    float s0 = 0.f, s1 = 0.f, s2 = 0.f, s3 = 0.f;
    int p = pb;
    for (; p + 4 <= pe; p += 4) {
        s0 += g_part[(size_t)(p + 0) * (U * PROW) + idx];
        s1 += g_part[(size_t)(p + 1) * (U * PROW) + idx];
        s2 += g_part[(size_t)(p + 2) * (U * PROW) + idx];
        s3 += g_part[(size_t)(p + 3) * (U * PROW) + idx];
    }
    for (; p < pe; p++) s0 += g_part[(size_t)p * (U * PROW) + idx];
    red[slice][ol] = (s0 + s1) + (s2 + s3);
    __syncthreads();
    if (slice == 0) {
        float t = 0.f;
        #pragma unroll
        for (int q = 0; q < 8; q++) t += red[q][ol];
        out[o] = t;
    }
}

extern "C" void kernel_launch(void* const* d_in, const int* in_sizes, int n_in,
                              void* d_out, int out_size) {
    const float* feats = (const float*)d_in[0];
    const float* means = (const float*)d_in[1];
    const float* lnv   = (const float*)d_in[2];
    const float* lp    = (const float*)d_in[3];
    const int*   candw = (const int*)d_in[4];

    int n  = in_sizes[0] / D;
    int nK = in_sizes[4];
    int probe_words = nK < 4096 ? nK : 4096;

    prep_kernel<<<U, D>>>(means, lnv, lp, candw, probe_words);

    int chunk = (n + GRID_B - 1) / GRID_B;
    size_t smem = (size_t)2 * SROUND * XROW * sizeof(float)
                + (size_t)U * CAP * sizeof(int2)
                + (size_t)U * (sizeof(int) + sizeof(float));
    cudaFuncSetAttribute(fused_kernel,
                         cudaFuncAttributeMaxDynamicSharedMemorySize, (int)smem);
    fused_kernel<<<GRID_B, THREADS_B, smem>>>(feats, candw, n, chunk);

    int total = U * (D + 1);
    reduce_kernel<<<(total + 63) / 64, 512>>>((float*)d_out);
}